// round 2
// baseline (speedup 1.0000x reference)
#include <cuda_runtime.h>
#include <cstdint>

// ============================================================================
// GaussianMLP fused kernel — sm_103 (non-'a' PTX target → NO tcgen05).
// Path: mma.sync.m16n8k8 tf32 (fp32 accum), fully fused:
//   h      = relu(x @ W_emb + b_emb)     [128x128]@[128x256]  (h stays in SMEM)
//   mean   = h @ W_mean + b_mean         [128x256]@[256x128]
//   logvar = h @ W_logvar + b_logvar     [128x256]@[256x128]
//   z      = mean + exp(0.5*logvar)*eps
// One CTA per 128-row tile, 8 warps (4M x 2N), accums in registers.
// ============================================================================

#define NTILES 4096

__device__ __forceinline__ float rna_tf32(float x) {
    float r;
    asm("cvt.rna.tf32.f32 %0, %1;" : "=f"(r) : "f"(x));
    return r;
}
__device__ __forceinline__ uint32_t as_u(float f) { return __float_as_uint(f); }

__device__ __forceinline__ void mma8(float* c, const uint32_t* a, uint32_t b0, uint32_t b1) {
    asm volatile(
        "mma.sync.aligned.m16n8k8.row.col.f32.tf32.tf32.f32 "
        "{%0,%1,%2,%3},{%4,%5,%6,%7},{%8,%9},{%0,%1,%2,%3};"
        : "+f"(c[0]), "+f"(c[1]), "+f"(c[2]), "+f"(c[3])
        : "r"(a[0]), "r"(a[1]), "r"(a[2]), "r"(a[3]), "r"(b0), "r"(b1));
}

// ---------------- pre-rounded weights (device globals) ----------------------
__device__ __align__(16) float g_wemb_f[128 * 256];   // [k][n] tf32-rounded
__device__ __align__(16) float g_w2[256 * 256];       // [k][ mean(0:128) | logvar(128:256) ]

__global__ void prep_kernel(const float* __restrict__ We,
                            const float* __restrict__ Wm,
                            const float* __restrict__ Wl) {
    int i = blockIdx.x * 256 + threadIdx.x;
    if (i < 32768) {
        g_wemb_f[i] = rna_tf32(We[i]);                 // already [k][n]
    } else if (i < 98304) {
        int j = i - 32768;
        int k = j >> 8, n = j & 255;
        float v = (n < 128) ? Wm[k * 128 + n] : Wl[k * 128 + (n - 128)];
        g_w2[j] = rna_tf32(v);
    }
}

// ---------------- SMEM map (bytes) ------------------------------------------
// hs  : h tile [128][260] fp32 (tf32-rounded)         133120   (reused: ms [128][132])
// xs  : x K-quarter [128][36]                          18432
// wb  : weight chunk (L1: [32][136] / L2: [64][264])   67584   (reused: ls [128][132])
// bias: b_emb 256f, b_mean 128f, b_lv 128f              2048
#define HS_OFF   0u
#define XS_OFF   133120u
#define WB_OFF   151552u
#define SBE_OFF  219136u
#define SBM_OFF  220160u
#define SBL_OFF  220672u
#define SMEM_TOTAL 221184
#define HS_S 260
#define XS_S 36
#define W1_S 136
#define W2_S 264
#define MS_S 132

__global__ void __launch_bounds__(256, 1)
gauss_kernel(const float* __restrict__ x, const float* __restrict__ eps,
             const float* __restrict__ be, const float* __restrict__ bm,
             const float* __restrict__ bl, float* __restrict__ out) {
    extern __shared__ char smem[];
    float* hs    = (float*)(smem + HS_OFF);
    float* xs    = (float*)(smem + XS_OFF);
    float* wb    = (float*)(smem + WB_OFF);
    float* sbemb = (float*)(smem + SBE_OFF);
    float* sbm   = (float*)(smem + SBM_OFF);
    float* sbl   = (float*)(smem + SBL_OFF);

    const int tid  = threadIdx.x;
    const int wid  = tid >> 5, lane = tid & 31;
    const int g    = lane >> 2, tg = lane & 3;       // mma fragment coords
    const int mw   = wid & 3, nw = wid >> 2;         // warp grid 4(M) x 2(N)
    const size_t tile = blockIdx.x;

    // biases
    sbemb[tid] = be[tid];
    if (tid < 128) { sbm[tid] = bm[tid]; sbl[tid] = bl[tid]; }

    const float4* xg = (const float4*)(x + tile * 16384);   // 128 rows x 32 f4

    // ======================= layer 1: h = relu(x @ We + b) ===================
    #pragma unroll 1
    for (int ni = 0; ni < 2; ni++) {
        float acc[2][8][4];
        #pragma unroll
        for (int m = 0; m < 2; m++)
            #pragma unroll
            for (int n = 0; n < 8; n++)
                #pragma unroll
                for (int c = 0; c < 4; c++) acc[m][n][c] = 0.0f;

        #pragma unroll 1
        for (int kq = 0; kq < 4; kq++) {
            __syncthreads();   // previous-stage reads (and bias init) complete
            // stage x quarter: [128 rows][32 k] (tf32-rounded)
            #pragma unroll
            for (int j = 0; j < 4; j++) {
                int i4 = tid + j * 256;               // 1024 float4
                int r = i4 >> 3, k4 = i4 & 7;
                float4 v = xg[r * 32 + kq * 8 + k4];
                v.x = rna_tf32(v.x); v.y = rna_tf32(v.y);
                v.z = rna_tf32(v.z); v.w = rna_tf32(v.w);
                *(float4*)&xs[r * XS_S + 4 * k4] = v;
            }
            // stage W_emb chunk: [32 k][128 n]
            #pragma unroll
            for (int j = 0; j < 4; j++) {
                int i4 = tid + j * 256;
                int kl = i4 >> 5, n4 = i4 & 31;
                float4 v = ((const float4*)g_wemb_f)[(kq * 32 + kl) * 64 + ni * 32 + n4];
                *(float4*)&wb[kl * W1_S + 4 * n4] = v;
            }
            __syncthreads();
            // 4 k-steps of K=8
            #pragma unroll
            for (int kk = 0; kk < 4; kk++) {
                uint32_t A[2][4];
                #pragma unroll
                for (int m = 0; m < 2; m++) {
                    int r0 = mw * 32 + m * 16 + g;
                    int kb = kk * 8 + tg;
                    A[m][0] = as_u(xs[r0 * XS_S + kb]);
                    A[m][1] = as_u(xs[(r0 + 8) * XS_S + kb]);
                    A[m][2] = as_u(xs[r0 * XS_S + kb + 4]);
                    A[m][3] = as_u(xs[(r0 + 8) * XS_S + kb + 4]);
                }
                #pragma unroll
                for (int n = 0; n < 8; n++) {
                    int c0 = nw * 64 + n * 8 + g;
                    uint32_t B0 = as_u(wb[(kk * 8 + tg) * W1_S + c0]);
                    uint32_t B1 = as_u(wb[(kk * 8 + tg + 4) * W1_S + c0]);
                    mma8(acc[0][n], A[0], B0, B1);
                    mma8(acc[1][n], A[1], B0, B1);
                }
            }
        }
        // write h chunk: bias + relu + tf32 round
        #pragma unroll
        for (int m = 0; m < 2; m++) {
            #pragma unroll
            for (int n = 0; n < 8; n++) {
                int col = ni * 128 + nw * 64 + n * 8 + 2 * tg;
                int r0  = mw * 32 + m * 16 + g;
                float b0v = sbemb[col], b1v = sbemb[col + 1];
                float2 v0, v1;
                v0.x = rna_tf32(fmaxf(acc[m][n][0] + b0v, 0.0f));
                v0.y = rna_tf32(fmaxf(acc[m][n][1] + b1v, 0.0f));
                v1.x = rna_tf32(fmaxf(acc[m][n][2] + b0v, 0.0f));
                v1.y = rna_tf32(fmaxf(acc[m][n][3] + b1v, 0.0f));
                *(float2*)&hs[r0 * HS_S + col]       = v0;
                *(float2*)&hs[(r0 + 8) * HS_S + col] = v1;
            }
        }
    }
    __syncthreads();   // hs complete, wb free

    // ============== layer 2: mean & logvar accums simultaneously =============
    float am[2][8][4], al[2][8][4];
    #pragma unroll
    for (int m = 0; m < 2; m++)
        #pragma unroll
        for (int n = 0; n < 8; n++)
            #pragma unroll
            for (int c = 0; c < 4; c++) { am[m][n][c] = 0.0f; al[m][n][c] = 0.0f; }

    #pragma unroll 1
    for (int kq = 0; kq < 4; kq++) {
        if (kq) __syncthreads();
        // stage W2 chunk: [64 k][256 n]  (mean cols 0:128, logvar 128:256)
        #pragma unroll
        for (int j = 0; j < 16; j++) {
            int i4 = tid + j * 256;                    // 4096 float4
            int kl = i4 >> 6, n4 = i4 & 63;
            float4 v = ((const float4*)g_w2)[(kq * 64 + kl) * 64 + n4];
            *(float4*)&wb[kl * W2_S + 4 * n4] = v;
        }
        __syncthreads();
        #pragma unroll
        for (int kk = 0; kk < 8; kk++) {
            uint32_t A[2][4];
            #pragma unroll
            for (int m = 0; m < 2; m++) {
                int r0 = mw * 32 + m * 16 + g;
                int kb = kq * 64 + kk * 8 + tg;
                A[m][0] = as_u(hs[r0 * HS_S + kb]);
                A[m][1] = as_u(hs[(r0 + 8) * HS_S + kb]);
                A[m][2] = as_u(hs[r0 * HS_S + kb + 4]);
                A[m][3] = as_u(hs[(r0 + 8) * HS_S + kb + 4]);
            }
            #pragma unroll
            for (int n = 0; n < 8; n++) {
                int c0 = nw * 64 + n * 8 + g;
                int kr0 = (kk * 8 + tg) * W2_S, kr1 = (kk * 8 + tg + 4) * W2_S;
                uint32_t Bm0 = as_u(wb[kr0 + c0]);
                uint32_t Bm1 = as_u(wb[kr1 + c0]);
                uint32_t Bl0 = as_u(wb[kr0 + 128 + c0]);
                uint32_t Bl1 = as_u(wb[kr1 + 128 + c0]);
                mma8(am[0][n], A[0], Bm0, Bm1);
                mma8(am[1][n], A[1], Bm0, Bm1);
                mma8(al[0][n], A[0], Bl0, Bl1);
                mma8(al[1][n], A[1], Bl0, Bl1);
            }
        }
    }
    __syncthreads();   // all hs/wb reads done — safe to overwrite

    // stage raw mean/logvar accums into SMEM (ms in hs region, ls in wb region)
    {
        float* ms = hs;
        float* ls = wb;
        #pragma unroll
        for (int m = 0; m < 2; m++) {
            #pragma unroll
            for (int n = 0; n < 8; n++) {
                int col = nw * 64 + n * 8 + 2 * tg;
                int r0  = mw * 32 + m * 16 + g;
                *(float2*)&ms[r0 * MS_S + col]       = make_float2(am[m][n][0], am[m][n][1]);
                *(float2*)&ms[(r0 + 8) * MS_S + col] = make_float2(am[m][n][2], am[m][n][3]);
                *(float2*)&ls[r0 * MS_S + col]       = make_float2(al[m][n][0], al[m][n][1]);
                *(float2*)&ls[(r0 + 8) * MS_S + col] = make_float2(al[m][n][2], al[m][n][3]);
            }
        }
    }
    __syncthreads();

    // ================= epilogue: z = mean + exp(0.5*logvar)*eps ==============
    {
        const float* ms = hs;
        const float* ls = wb;
        const float4* eg = (const float4*)(eps + tile * 16384);
        float4* oz = (float4*)out + tile * 4096;
        float4* om = (float4*)out + 16777216u + tile * 4096;
        float4* ol = (float4*)out + 33554432u + tile * 4096;
        #pragma unroll
        for (int j = 0; j < 16; j++) {
            int idx = tid + j * 256;                   // 4096 float4
            int r = idx >> 5, c4 = idx & 31;
            int c = 4 * c4;
            float4 m4 = *(const float4*)&ms[r * MS_S + c];
            float4 l4 = *(const float4*)&ls[r * MS_S + c];
            m4.x += sbm[c];     m4.y += sbm[c + 1];
            m4.z += sbm[c + 2]; m4.w += sbm[c + 3];
            l4.x += sbl[c];     l4.y += sbl[c + 1];
            l4.z += sbl[c + 2]; l4.w += sbl[c + 3];
            float4 e4 = eg[idx];
            float4 z4;
            z4.x = fmaf(__expf(0.5f * l4.x), e4.x, m4.x);
            z4.y = fmaf(__expf(0.5f * l4.y), e4.y, m4.y);
            z4.z = fmaf(__expf(0.5f * l4.z), e4.z, m4.z);
            z4.w = fmaf(__expf(0.5f * l4.w), e4.w, m4.w);
            oz[idx] = z4;
            om[idx] = m4;
            ol[idx] = l4;
        }
    }
}

// ---------------------------------------------------------------------------

extern "C" void kernel_launch(void* const* d_in, const int* in_sizes, int n_in,
                              void* d_out, int out_size) {
    const float* x   = (const float*)d_in[0];
    const float* eps = (const float*)d_in[1];
    const float* We  = (const float*)d_in[2];
    const float* be  = (const float*)d_in[3];
    const float* Wm  = (const float*)d_in[4];
    const float* bm  = (const float*)d_in[5];
    const float* Wl  = (const float*)d_in[6];
    const float* bl  = (const float*)d_in[7];
    float* out = (float*)d_out;

    cudaFuncSetAttribute(gauss_kernel, cudaFuncAttributeMaxDynamicSharedMemorySize, SMEM_TOTAL);
    prep_kernel<<<384, 256>>>(We, Wm, Wl);
    gauss_kernel<<<NTILES, 256, SMEM_TOTAL>>>(x, eps, be, bm, bl, out);
}

// round 3
// speedup vs baseline: 1.0164x; 1.0164x over previous
#include <cuda_runtime.h>
#include <cstdint>

// ============================================================================
// GaussianMLP fused — sm_103 plain target: mma.sync m16n8k8 tf32 path.
// R3: 512 threads (16 warps), cp.async double-buffered staging, ldmatrix frags.
//   warp tile: M=16 x N=128; layer2: warps 0-7 -> mean, warps 8-15 -> logvar.
// ============================================================================

#define NTILES 4096

__device__ __forceinline__ uint32_t smem_u32(const void* p) {
    uint32_t a;
    asm("{ .reg .u64 t; cvta.to.shared.u64 t, %1; cvt.u32.u64 %0, t; }" : "=r"(a) : "l"(p));
    return a;
}
__device__ __forceinline__ float rna_tf32(float x) {
    float r;
    asm("cvt.rna.tf32.f32 %0, %1;" : "=f"(r) : "f"(x));
    return r;
}
__device__ __forceinline__ void mma8(float* c, const uint32_t* a, uint32_t b0, uint32_t b1) {
    asm volatile(
        "mma.sync.aligned.m16n8k8.row.col.f32.tf32.tf32.f32 "
        "{%0,%1,%2,%3},{%4,%5,%6,%7},{%8,%9},{%0,%1,%2,%3};"
        : "+f"(c[0]), "+f"(c[1]), "+f"(c[2]), "+f"(c[3])
        : "r"(a[0]), "r"(a[1]), "r"(a[2]), "r"(a[3]), "r"(b0), "r"(b1));
}
__device__ __forceinline__ void ldsm4(uint32_t* r, uint32_t addr) {
    asm volatile("ldmatrix.sync.aligned.m8n8.x4.shared.b16 {%0,%1,%2,%3}, [%4];"
                 : "=r"(r[0]), "=r"(r[1]), "=r"(r[2]), "=r"(r[3]) : "r"(addr));
}
#define CP16(dst, src) \
    asm volatile("cp.async.ca.shared.global [%0], [%1], 16;" :: "r"(dst), "l"(src))
#define CP_COMMIT() asm volatile("cp.async.commit_group;" ::: "memory")
#define CP_WAIT1()  asm volatile("cp.async.wait_group 1;" ::: "memory")
#define CP_WAIT0()  asm volatile("cp.async.wait_group 0;" ::: "memory")

// ---------------- pre-rounded, pre-transposed weights ------------------------
__device__ __align__(16) float g_wemb_t[256 * 128];   // [n][k]  (We is [k=128][n=256])
__device__ __align__(16) float g_w2_t[256 * 256];     // [n][k]  n<128: Wm, n>=128: Wl

__global__ void prep_kernel(const float* __restrict__ We,
                            const float* __restrict__ Wm,
                            const float* __restrict__ Wl) {
    int i = blockIdx.x * 256 + threadIdx.x;
    if (i < 32768) {
        int n = i >> 7, k = i & 127;
        g_wemb_t[i] = rna_tf32(We[k * 256 + n]);
    } else if (i < 98304) {
        int j = i - 32768;
        int n = j >> 8, k = j & 255;
        float v = (n < 128) ? Wm[k * 128 + n] : Wl[k * 128 + (n - 128)];
        g_w2_t[j] = rna_tf32(v);
    }
}

// ---------------- SMEM map (bytes) ------------------------------------------
// hs : h tile [128][260]                          133120  (xs bufs live inside
//      during layer1; reused as ms/ls for epilogue)
// wb : weight stage bufs 2 x [256][36]             73728
// bias                                              2048
#define HS_OFF   0u
#define XS0_OFF  0u
#define XS1_OFF  18432u
#define WB0_OFF  133120u
#define WB1_OFF  169984u
#define SBE_OFF  206848u
#define SBM_OFF  207872u
#define SBL_OFF  208384u
#define SMEM_TOTAL 208896
#define HS_S 260
#define XW_S 36          // xs and wb row stride (floats)
#define MS_S 132
#define MS1_OFF 67584u   // ls region inside hs

__global__ void __launch_bounds__(512, 1)
gauss_kernel(const float* __restrict__ x, const float* __restrict__ eps,
             const float* __restrict__ be, const float* __restrict__ bm,
             const float* __restrict__ bl, float* __restrict__ out) {
    extern __shared__ char smem[];
    const uint32_t sm = smem_u32(smem);
    float* hs  = (float*)(smem + HS_OFF);
    float* sbe = (float*)(smem + SBE_OFF);
    float* sbm = (float*)(smem + SBM_OFF);
    float* sbl = (float*)(smem + SBL_OFF);

    const int tid  = threadIdx.x;
    const int wid  = tid >> 5, lane = tid & 31;
    const int g    = lane >> 2, tg = lane & 3;
    const int mw   = wid & 7;                 // M block (16 rows each)
    const int cb   = (wid >> 3) * 128;        // column-block / output selector
    const size_t tile = blockIdx.x;

    // per-lane ldmatrix address components
    const int a_row  = (lane & 7) + ((lane & 8) ? 8 : 0);
    const int a_koff = (lane & 16) ? 4 : 0;
    const int b_n    = (lane & 7) + ((lane & 16) ? 8 : 0);
    const int b_koff = (lane & 8) ? 4 : 0;

    if (tid < 256) sbe[tid] = be[tid];
    if (tid < 128) { sbm[tid] = bm[tid]; sbl[tid] = bl[tid]; }

    const float* xg = x + tile * 16384;

    // staging index helpers (per thread)
    const int s_row = tid >> 3, s_q = tid & 7;   // row/quarter for 512-thread copies

    // ---- stage-issue lambdas ----
    auto issue_w = [&](const float* src, int sstride, int kbase, uint32_t dstbase) {
        #pragma unroll
        for (int j = 0; j < 4; j++) {
            int row = s_row + j * 64;
            const float* gp = src + row * sstride + kbase + s_q * 4;
            uint32_t sa = dstbase + (uint32_t)(row * XW_S + s_q * 4) * 4u;
            CP16(sa, gp);
        }
    };
    auto issue_x = [&](int kq, uint32_t dstbase) {
        #pragma unroll
        for (int j = 0; j < 2; j++) {
            int row = s_row + j * 64;
            const float* gp = xg + row * 128 + kq * 32 + s_q * 4;
            uint32_t sa = dstbase + (uint32_t)(row * XW_S + s_q * 4) * 4u;
            CP16(sa, gp);
        }
    };

    const uint32_t xsb[2] = { sm + XS0_OFF, sm + XS1_OFF };
    const uint32_t wbb[2] = { sm + WB0_OFF, sm + WB1_OFF };

    float acc[16][4];
    #pragma unroll
    for (int n = 0; n < 16; n++)
        #pragma unroll
        for (int c = 0; c < 4; c++) acc[n][c] = 0.0f;

    // prologue: stage 0 (x q0 + W1 chunk0)
    issue_x(0, xsb[0]);
    issue_w(g_wemb_t, 128, 0, wbb[0]);
    CP_COMMIT();

    // ======================= layer 1 (stages 0..3) ===========================
    #pragma unroll 1
    for (int s = 0; s < 4; s++) {
        const int cur = s & 1, nxt = cur ^ 1;
        __syncthreads();                       // prev MMA reads of buf[nxt] done
        if (s < 3) {
            issue_x(s + 1, xsb[nxt]);
            issue_w(g_wemb_t, 128, (s + 1) * 32, wbb[nxt]);
            CP_COMMIT(); CP_WAIT1();
        } else {
            issue_w(g_w2_t, 256, 0, wbb[nxt]); // prefetch layer-2 chunk 0
            CP_COMMIT(); CP_WAIT1();
        }
        __syncthreads();                       // buf[cur] visible

        const uint32_t a_base = xsb[cur] + (uint32_t)((mw * 16 + a_row) * XW_S + a_koff) * 4u;
        const uint32_t b_base = wbb[cur] + (uint32_t)((cb + b_n) * XW_S + b_koff) * 4u;
        #pragma unroll
        for (int kk = 0; kk < 4; kk++) {
            uint32_t A[4];
            ldsm4(A, a_base + kk * 32u);
            #pragma unroll
            for (int c = 0; c < 4; c++)
                A[c] = __float_as_uint(rna_tf32(__uint_as_float(A[c])));
            #pragma unroll
            for (int p = 0; p < 8; p++) {
                uint32_t B[4];
                ldsm4(B, b_base + (uint32_t)(p * 16 * XW_S) * 4u + kk * 32u);
                mma8(acc[2 * p],     A, B[0], B[1]);
                mma8(acc[2 * p + 1], A, B[2], B[3]);
            }
        }
    }

    // ---- write h = tf32(relu(acc + b_emb)) ----
    __syncthreads();                           // xs reads done; hs region free
    {
        const int r0 = mw * 16 + g;
        #pragma unroll
        for (int n = 0; n < 16; n++) {
            int col = cb + n * 8 + 2 * tg;
            float b0v = sbe[col], b1v = sbe[col + 1];
            float2 v0, v1;
            v0.x = rna_tf32(fmaxf(acc[n][0] + b0v, 0.0f));
            v0.y = rna_tf32(fmaxf(acc[n][1] + b1v, 0.0f));
            v1.x = rna_tf32(fmaxf(acc[n][2] + b0v, 0.0f));
            v1.y = rna_tf32(fmaxf(acc[n][3] + b1v, 0.0f));
            *(float2*)&hs[r0 * HS_S + col]       = v0;
            *(float2*)&hs[(r0 + 8) * HS_S + col] = v1;
        }
    }

    #pragma unroll
    for (int n = 0; n < 16; n++)
        #pragma unroll
        for (int c = 0; c < 4; c++) acc[n][c] = 0.0f;

    // ======================= layer 2 (chunks 0..7) ===========================
    #pragma unroll 1
    for (int c8 = 0; c8 < 8; c8++) {
        const int cur = c8 & 1, nxt = cur ^ 1;
        __syncthreads();
        if (c8 < 7) { issue_w(g_w2_t, 256, (c8 + 1) * 32, wbb[nxt]); CP_COMMIT(); CP_WAIT1(); }
        else        { CP_WAIT0(); }
        __syncthreads();

        const uint32_t a_base = sm + HS_OFF
            + (uint32_t)((mw * 16 + a_row) * HS_S + c8 * 32 + a_koff) * 4u;
        const uint32_t b_base = wbb[cur] + (uint32_t)((cb + b_n) * XW_S + b_koff) * 4u;
        #pragma unroll
        for (int kk = 0; kk < 4; kk++) {
            uint32_t A[4];
            ldsm4(A, a_base + kk * 32u);       // h pre-rounded: no cvt
            #pragma unroll
            for (int p = 0; p < 8; p++) {
                uint32_t B[4];
                ldsm4(B, b_base + (uint32_t)(p * 16 * XW_S) * 4u + kk * 32u);
                mma8(acc[2 * p],     A, B[0], B[1]);
                mma8(acc[2 * p + 1], A, B[2], B[3]);
            }
        }
    }
    __syncthreads();                           // all hs reads done — reuse as ms/ls

    // ---- stage raw mean/logvar accums to SMEM (warps 0-7: mean, 8-15: logvar)
    {
        float* dst = (cb == 0) ? (float*)(smem + HS_OFF) : (float*)(smem + MS1_OFF);
        const int r0 = mw * 16 + g;
        #pragma unroll
        for (int n = 0; n < 16; n++) {
            int col = n * 8 + 2 * tg;
            *(float2*)&dst[r0 * MS_S + col]       = make_float2(acc[n][0], acc[n][1]);
            *(float2*)&dst[(r0 + 8) * MS_S + col] = make_float2(acc[n][2], acc[n][3]);
        }
    }
    __syncthreads();

    // ---- epilogue: z = mean + exp(0.5*logvar)*eps ; coalesced stores --------
    {
        const float* ms = (const float*)(smem + HS_OFF);
        const float* ls = (const float*)(smem + MS1_OFF);
        const float4* eg = (const float4*)(eps + tile * 16384);
        float4* oz = (float4*)out + tile * 4096;
        float4* om = (float4*)out + 16777216u + tile * 4096;
        float4* ol = (float4*)out + 33554432u + tile * 4096;
        #pragma unroll
        for (int j = 0; j < 8; j++) {
            int idx = tid + j * 512;
            int r = idx >> 5, c4 = idx & 31;
            int c = 4 * c4;
            float4 m4 = *(const float4*)&ms[r * MS_S + c];
            float4 l4 = *(const float4*)&ls[r * MS_S + c];
            m4.x += sbm[c];     m4.y += sbm[c + 1];
            m4.z += sbm[c + 2]; m4.w += sbm[c + 3];
            l4.x += sbl[c];     l4.y += sbl[c + 1];
            l4.z += sbl[c + 2]; l4.w += sbl[c + 3];
            float4 e4 = eg[idx];
            float4 z4;
            z4.x = fmaf(__expf(0.5f * l4.x), e4.x, m4.x);
            z4.y = fmaf(__expf(0.5f * l4.y), e4.y, m4.y);
            z4.z = fmaf(__expf(0.5f * l4.z), e4.z, m4.z);
            z4.w = fmaf(__expf(0.5f * l4.w), e4.w, m4.w);
            oz[idx] = z4;
            om[idx] = m4;
            ol[idx] = l4;
        }
    }
}

// ---------------------------------------------------------------------------

extern "C" void kernel_launch(void* const* d_in, const int* in_sizes, int n_in,
                              void* d_out, int out_size) {
    const float* x   = (const float*)d_in[0];
    const float* eps = (const float*)d_in[1];
    const float* We  = (const float*)d_in[2];
    const float* be  = (const float*)d_in[3];
    const float* Wm  = (const float*)d_in[4];
    const float* bm  = (const float*)d_in[5];
    const float* Wl  = (const float*)d_in[6];
    const float* bl  = (const float*)d_in[7];
    float* out = (float*)d_out;

    cudaFuncSetAttribute(gauss_kernel, cudaFuncAttributeMaxDynamicSharedMemorySize, SMEM_TOTAL);
    prep_kernel<<<384, 256>>>(We, Wm, Wl);
    gauss_kernel<<<NTILES, 512, SMEM_TOTAL>>>(x, eps, be, bm, bl, out);
}

// round 4
// speedup vs baseline: 1.0182x; 1.0018x over previous
#include <cuda_runtime.h>
#include <cstdint>

// ============================================================================
// GaussianMLP fused — sm_103 plain target, mma.sync m16n8k8 tf32.
// R4: warp tile M=32 x N=64 (4x4 warp grid) to halve B-fragment SMEM traffic;
//     register-direct epilogue (only logvar crosses warps via SMEM).
// ============================================================================

#define NTILES 4096

__device__ __forceinline__ uint32_t smem_u32(const void* p) {
    uint32_t a;
    asm("{ .reg .u64 t; cvta.to.shared.u64 t, %1; cvt.u32.u64 %0, t; }" : "=r"(a) : "l"(p));
    return a;
}
__device__ __forceinline__ float rna_tf32(float x) {
    float r;
    asm("cvt.rna.tf32.f32 %0, %1;" : "=f"(r) : "f"(x));
    return r;
}
__device__ __forceinline__ void mma8(float* c, const uint32_t* a, uint32_t b0, uint32_t b1) {
    asm volatile(
        "mma.sync.aligned.m16n8k8.row.col.f32.tf32.tf32.f32 "
        "{%0,%1,%2,%3},{%4,%5,%6,%7},{%8,%9},{%0,%1,%2,%3};"
        : "+f"(c[0]), "+f"(c[1]), "+f"(c[2]), "+f"(c[3])
        : "r"(a[0]), "r"(a[1]), "r"(a[2]), "r"(a[3]), "r"(b0), "r"(b1));
}
__device__ __forceinline__ void ldsm4(uint32_t* r, uint32_t addr) {
    asm volatile("ldmatrix.sync.aligned.m8n8.x4.shared.b16 {%0,%1,%2,%3}, [%4];"
                 : "=r"(r[0]), "=r"(r[1]), "=r"(r[2]), "=r"(r[3]) : "r"(addr));
}
#define CP16(dst, src) \
    asm volatile("cp.async.ca.shared.global [%0], [%1], 16;" :: "r"(dst), "l"(src))
#define CP_COMMIT() asm volatile("cp.async.commit_group;" ::: "memory")
#define CP_WAIT1()  asm volatile("cp.async.wait_group 1;" ::: "memory")
#define CP_WAIT0()  asm volatile("cp.async.wait_group 0;" ::: "memory")

// ---------------- pre-rounded, pre-transposed weights ------------------------
__device__ __align__(16) float g_wemb_t[256 * 128];   // [n][k]
__device__ __align__(16) float g_w2_t[256 * 256];     // [n][k]  n<128: Wm, else Wl

__global__ void prep_kernel(const float* __restrict__ We,
                            const float* __restrict__ Wm,
                            const float* __restrict__ Wl) {
    int i = blockIdx.x * 256 + threadIdx.x;
    if (i < 32768) {
        int n = i >> 7, k = i & 127;
        g_wemb_t[i] = rna_tf32(We[k * 256 + n]);
    } else if (i < 98304) {
        int j = i - 32768;
        int n = j >> 8, k = j & 255;
        float v = (n < 128) ? Wm[k * 128 + n] : Wl[k * 128 + (n - 128)];
        g_w2_t[j] = rna_tf32(v);
    }
}

// ---------------- SMEM map ---------------------------------------------------
#define HS_OFF   0u
#define XS0_OFF  0u
#define XS1_OFF  18432u
#define WB0_OFF  133120u
#define WB1_OFF  169984u
#define SBE_OFF  206848u
#define SBM_OFF  207872u
#define SBL_OFF  208384u
#define SMEM_TOTAL 208896
#define HS_S 260
#define XW_S 36
#define MS_S 132          // logvar exchange tile stride (in hs region)

__global__ void __launch_bounds__(512, 1)
gauss_kernel(const float* __restrict__ x, const float* __restrict__ eps,
             const float* __restrict__ be, const float* __restrict__ bm,
             const float* __restrict__ bl, float* __restrict__ out) {
    extern __shared__ char smem[];
    const uint32_t sm = smem_u32(smem);
    float* hs  = (float*)(smem + HS_OFF);
    float* sbe = (float*)(smem + SBE_OFF);
    float* sbm = (float*)(smem + SBM_OFF);
    float* sbl = (float*)(smem + SBL_OFF);

    const int tid  = threadIdx.x;
    const int wid  = tid >> 5, lane = tid & 31;
    const int g    = lane >> 2, tg = lane & 3;
    const int mw   = wid & 3;                 // M block: 32 rows
    const int nw   = wid >> 2;                // N block: 64 cols (of 256)
    const int nb   = nw * 64;
    const size_t tile = blockIdx.x;

    // ldmatrix lane address components
    const int a_row  = (lane & 7) + ((lane & 8) ? 8 : 0);
    const int a_koff = (lane & 16) ? 4 : 0;
    const int b_n    = (lane & 7) + ((lane & 16) ? 8 : 0);
    const int b_koff = (lane & 8) ? 4 : 0;

    if (tid < 256) sbe[tid] = be[tid];
    if (tid < 128) { sbm[tid] = bm[tid]; sbl[tid] = bl[tid]; }

    const float* xg = x + tile * 16384;
    const int s_row = tid >> 3, s_q = tid & 7;

    auto issue_w = [&](const float* src, int sstride, int kbase, uint32_t dstbase) {
        #pragma unroll
        for (int j = 0; j < 4; j++) {
            int row = s_row + j * 64;
            const float* gp = src + row * sstride + kbase + s_q * 4;
            uint32_t sa = dstbase + (uint32_t)(row * XW_S + s_q * 4) * 4u;
            CP16(sa, gp);
        }
    };
    auto issue_x = [&](int kq, uint32_t dstbase) {
        #pragma unroll
        for (int j = 0; j < 2; j++) {
            int row = s_row + j * 64;
            const float* gp = xg + row * 128 + kq * 32 + s_q * 4;
            uint32_t sa = dstbase + (uint32_t)(row * XW_S + s_q * 4) * 4u;
            CP16(sa, gp);
        }
    };

    const uint32_t xsb[2] = { sm + XS0_OFF, sm + XS1_OFF };
    const uint32_t wbb[2] = { sm + WB0_OFF, sm + WB1_OFF };

    float acc[2][8][4];
    #pragma unroll
    for (int m = 0; m < 2; m++)
        #pragma unroll
        for (int n = 0; n < 8; n++)
            #pragma unroll
            for (int c = 0; c < 4; c++) acc[m][n][c] = 0.0f;

    issue_x(0, xsb[0]);
    issue_w(g_wemb_t, 128, 0, wbb[0]);
    CP_COMMIT();

    // ======================= layer 1 (4 stages of K=32) ======================
    #pragma unroll 1
    for (int s = 0; s < 4; s++) {
        const int cur = s & 1, nxt = cur ^ 1;
        __syncthreads();
        if (s < 3) {
            issue_x(s + 1, xsb[nxt]);
            issue_w(g_wemb_t, 128, (s + 1) * 32, wbb[nxt]);
            CP_COMMIT(); CP_WAIT1();
        } else {
            issue_w(g_w2_t, 256, 0, wbb[nxt]);
            CP_COMMIT(); CP_WAIT1();
        }
        __syncthreads();

        const uint32_t a0 = xsb[cur] + (uint32_t)((mw * 32 + a_row) * XW_S + a_koff) * 4u;
        const uint32_t b0 = wbb[cur] + (uint32_t)((nb + b_n) * XW_S + b_koff) * 4u;
        #pragma unroll
        for (int kk = 0; kk < 4; kk++) {
            uint32_t A[2][4];
            #pragma unroll
            for (int m = 0; m < 2; m++) {
                ldsm4(A[m], a0 + (uint32_t)(m * 16 * XW_S) * 4u + kk * 32u);
                #pragma unroll
                for (int c = 0; c < 4; c++)
                    A[m][c] = __float_as_uint(rna_tf32(__uint_as_float(A[m][c])));
            }
            #pragma unroll
            for (int p = 0; p < 4; p++) {
                uint32_t B[4];
                ldsm4(B, b0 + (uint32_t)(p * 16 * XW_S) * 4u + kk * 32u);
                #pragma unroll
                for (int m = 0; m < 2; m++) {
                    mma8(acc[m][2 * p],     A[m], B[0], B[1]);
                    mma8(acc[m][2 * p + 1], A[m], B[2], B[3]);
                }
            }
        }
    }

    // ---- h = tf32(relu(acc + b_emb)) -> SMEM ----
    __syncthreads();
    {
        #pragma unroll
        for (int m = 0; m < 2; m++) {
            const int r0 = mw * 32 + m * 16 + g;
            #pragma unroll
            for (int n = 0; n < 8; n++) {
                int col = nb + n * 8 + 2 * tg;
                float b0v = sbe[col], b1v = sbe[col + 1];
                float2 v0, v1;
                v0.x = rna_tf32(fmaxf(acc[m][n][0] + b0v, 0.0f));
                v0.y = rna_tf32(fmaxf(acc[m][n][1] + b1v, 0.0f));
                v1.x = rna_tf32(fmaxf(acc[m][n][2] + b0v, 0.0f));
                v1.y = rna_tf32(fmaxf(acc[m][n][3] + b1v, 0.0f));
                *(float2*)&hs[r0 * HS_S + col]       = v0;
                *(float2*)&hs[(r0 + 8) * HS_S + col] = v1;
            }
        }
    }

    #pragma unroll
    for (int m = 0; m < 2; m++)
        #pragma unroll
        for (int n = 0; n < 8; n++)
            #pragma unroll
            for (int c = 0; c < 4; c++) acc[m][n][c] = 0.0f;

    // ======================= layer 2 (8 chunks of K=32) ======================
    #pragma unroll 1
    for (int c8 = 0; c8 < 8; c8++) {
        const int cur = c8 & 1, nxt = cur ^ 1;
        __syncthreads();
        if (c8 < 7) { issue_w(g_w2_t, 256, (c8 + 1) * 32, wbb[nxt]); CP_COMMIT(); CP_WAIT1(); }
        else        { CP_WAIT0(); }
        __syncthreads();

        const uint32_t a0 = sm + HS_OFF
            + (uint32_t)((mw * 32 + a_row) * HS_S + c8 * 32 + a_koff) * 4u;
        const uint32_t b0 = wbb[cur] + (uint32_t)((nb + b_n) * XW_S + b_koff) * 4u;
        #pragma unroll
        for (int kk = 0; kk < 4; kk++) {
            uint32_t A[2][4];
            #pragma unroll
            for (int m = 0; m < 2; m++)
                ldsm4(A[m], a0 + (uint32_t)(m * 16 * HS_S) * 4u + kk * 32u);
            #pragma unroll
            for (int p = 0; p < 4; p++) {
                uint32_t B[4];
                ldsm4(B, b0 + (uint32_t)(p * 16 * XW_S) * 4u + kk * 32u);
                #pragma unroll
                for (int m = 0; m < 2; m++) {
                    mma8(acc[m][2 * p],     A[m], B[0], B[1]);
                    mma8(acc[m][2 * p + 1], A[m], B[2], B[3]);
                }
            }
        }
    }
    __syncthreads();   // hs reads complete — region reusable for logvar exchange

    // ============== epilogue: register-direct, fragment layout ===============
    // warps nw>=2 own logvar (cols 128..255): add bias, store to gmem + SMEM.
    if (nw >= 2) {
        float* ls = (float*)smem;              // [128][MS_S]
        const int cb2 = nb - 128;
        float* olg = out + 134217728u + tile * 16384;
        #pragma unroll
        for (int m = 0; m < 2; m++) {
            const int rA = mw * 32 + m * 16 + g, rB = rA + 8;
            #pragma unroll
            for (int n = 0; n < 8; n++) {
                int cc = cb2 + n * 8 + 2 * tg;
                float b0v = sbl[cc], b1v = sbl[cc + 1];
                float2 v0 = make_float2(acc[m][n][0] + b0v, acc[m][n][1] + b1v);
                float2 v1 = make_float2(acc[m][n][2] + b0v, acc[m][n][3] + b1v);
                *(float2*)&ls[rA * MS_S + cc] = v0;
                *(float2*)&ls[rB * MS_S + cc] = v1;
                *(float2*)&olg[rA * 128 + cc] = v0;
                *(float2*)&olg[rB * 128 + cc] = v1;
            }
        }
    }
    __syncthreads();
    // warps nw<2 own mean (cols 0..127): read logvar from SMEM, compute z.
    if (nw < 2) {
        const float* ls = (const float*)smem;
        const float* eg = eps + tile * 16384;
        float* oz = out + tile * 16384;
        float* om = out + 67108864u + tile * 16384;
        #pragma unroll
        for (int m = 0; m < 2; m++) {
            const int rA = mw * 32 + m * 16 + g, rB = rA + 8;
            #pragma unroll
            for (int n = 0; n < 8; n++) {
                int cc = nb + n * 8 + 2 * tg;
                float b0v = sbm[cc], b1v = sbm[cc + 1];
                float2 m0 = make_float2(acc[m][n][0] + b0v, acc[m][n][1] + b1v);
                float2 m1 = make_float2(acc[m][n][2] + b0v, acc[m][n][3] + b1v);
                float2 l0 = *(const float2*)&ls[rA * MS_S + cc];
                float2 l1 = *(const float2*)&ls[rB * MS_S + cc];
                float2 e0 = *(const float2*)&eg[rA * 128 + cc];
                float2 e1 = *(const float2*)&eg[rB * 128 + cc];
                float2 z0, z1;
                z0.x = fmaf(__expf(0.5f * l0.x), e0.x, m0.x);
                z0.y = fmaf(__expf(0.5f * l0.y), e0.y, m0.y);
                z1.x = fmaf(__expf(0.5f * l1.x), e1.x, m1.x);
                z1.y = fmaf(__expf(0.5f * l1.y), e1.y, m1.y);
                *(float2*)&oz[rA * 128 + cc] = z0;
                *(float2*)&oz[rB * 128 + cc] = z1;
                *(float2*)&om[rA * 128 + cc] = m0;
                *(float2*)&om[rB * 128 + cc] = m1;
            }
        }
    }
}

// ---------------------------------------------------------------------------

extern "C" void kernel_launch(void* const* d_in, const int* in_sizes, int n_in,
                              void* d_out, int out_size) {
    const float* x   = (const float*)d_in[0];
    const float* eps = (const float*)d_in[1];
    const float* We  = (const float*)d_in[2];
    const float* be  = (const float*)d_in[3];
    const float* Wm  = (const float*)d_in[4];
    const float* bm  = (const float*)d_in[5];
    const float* Wl  = (const float*)d_in[6];
    const float* bl  = (const float*)d_in[7];
    float* out = (float*)d_out;

    cudaFuncSetAttribute(gauss_kernel, cudaFuncAttributeMaxDynamicSharedMemorySize, SMEM_TOTAL);
    prep_kernel<<<384, 256>>>(We, Wm, Wl);
    gauss_kernel<<<NTILES, 512, SMEM_TOTAL>>>(x, eps, be, bm, bl, out);
}